// round 13
// baseline (speedup 1.0000x reference)
#include <cuda_runtime.h>
#include <cstdint>

using ull = unsigned long long;
#define NTHREADS 256

__device__ __forceinline__ void fma2(ull& d, ull a, ull b) {
    asm("fma.rn.f32x2 %0, %1, %2, %0;" : "+l"(d) : "l"(a), "l"(b));
}
__device__ __forceinline__ ull dup2(float x) {
    ull d; unsigned xi = __float_as_uint(x);
    asm("mov.b64 %0, {%1, %1};" : "=l"(d) : "r"(xi));
    return d;
}
__device__ __forceinline__ float ulo(ull v) { return __uint_as_float((unsigned)v); }
__device__ __forceinline__ float uhi(ull v) { return __uint_as_float((unsigned)(v >> 32)); }
__device__ __forceinline__ void cp_async8(void* dst, const void* src) {
    unsigned s = (unsigned)__cvta_generic_to_shared(dst);
    asm volatile("cp.async.ca.shared.global [%0], [%1], 8;" :: "r"(s), "l"(src));
}
__device__ __forceinline__ void cp_commit() { asm volatile("cp.async.commit_group;"); }
__device__ __forceinline__ void cp_wait1() { asm volatile("cp.async.wait_group 1;" ::: "memory"); }

// ---------------------------------------------------------------------------
// 0e: out[n,o] = sum_i x[n,i]*w[o,i] + bias[o];  I=O=128
// 8 warps: warp=grp owns outputs [16w,16w+16); lane owns 4 nodes (n=4,p=8)
// ---------------------------------------------------------------------------
__device__ void body_k0e(int cta, int ncta,
                         const float* __restrict__ x, const float* __restrict__ w,
                         const float* __restrict__ bias, float* __restrict__ out,
                         int N, float* sm) {
    constexpr int K = 128, TILE = 128, XROW = 132, WROW = 132;
    constexpr int WS = 128 * WROW;       // 16896
    constexpr int XB = TILE * XROW;      // 16896
    constexpr int CH = TILE * (K / 2);   // 8192

    float* ws  = sm;
    float* xb0 = sm + WS;
    float* xb1 = sm + WS + XB;
    float* bs  = sm + WS + 2 * XB;

    int tid = threadIdx.x;
    for (int idx = tid; idx < 128 * 128; idx += NTHREADS)
        ws[(idx & 127) * WROW + (idx >> 7)] = w[idx];      // ws[i][o]
    if (tid < 128) bs[tid] = bias[tid];

    int warp = tid >> 5, lane = tid & 31;
    int ntiles = (N + TILE - 1) / TILE;
    int t0 = cta;

    if (t0 < ntiles) {
        long long base = (long long)t0 * TILE;
        for (int c = tid; c < CH; c += NTHREADS) {
            int nd = c >> 6, cq = c & 63;
            long long n = base + nd;
            if (n < N) cp_async8(xb0 + nd * XROW + cq * 2, x + n * K + cq * 2);
        }
    }
    cp_commit();

    int par = 0;
    for (int t = t0; t < ntiles; t += ncta, par ^= 1) {
        int tn = t + ncta;
        if (tn < ntiles) {
            long long base = (long long)tn * TILE;
            float* dst = par ? xb0 : xb1;
            for (int c = tid; c < CH; c += NTHREADS) {
                int nd = c >> 6, cq = c & 63;
                long long n = base + nd;
                if (n < N) cp_async8(dst + nd * XROW + cq * 2, x + n * K + cq * 2);
            }
        }
        cp_commit();
        cp_wait1();
        __syncthreads();

        float* xa = par ? xb1 : xb0;
        const float4* xr[4];
        #pragma unroll
        for (int q = 0; q < 4; q++)
            xr[q] = (const float4*)(xa + (lane + 32 * q) * XROW);

        ull acc[4][8];
        const ull* bs2 = (const ull*)bs;
        #pragma unroll
        for (int q = 0; q < 4; q++)
            #pragma unroll
            for (int j = 0; j < 8; j++) acc[q][j] = bs2[warp * 8 + j];

        #pragma unroll 2
        for (int k4 = 0; k4 < K / 4; k4++) {
            float xs[4][4];
            #pragma unroll
            for (int q = 0; q < 4; q++) *(float4*)&xs[q][0] = xr[q][k4];
            #pragma unroll
            for (int kk = 0; kk < 4; kk++) {
                const ulonglong2* wr =
                    (const ulonglong2*)(ws + (k4 * 4 + kk) * WROW) + warp * 4;
                ulonglong2 u0 = wr[0], u1 = wr[1], u2 = wr[2], u3 = wr[3];
                #pragma unroll
                for (int q = 0; q < 4; q++) {
                    ull xd = dup2(xs[q][kk]);
                    fma2(acc[q][0], xd, u0.x); fma2(acc[q][1], xd, u0.y);
                    fma2(acc[q][2], xd, u1.x); fma2(acc[q][3], xd, u1.y);
                    fma2(acc[q][4], xd, u2.x); fma2(acc[q][5], xd, u2.y);
                    fma2(acc[q][6], xd, u3.x); fma2(acc[q][7], xd, u3.y);
                }
            }
        }

        long long base = (long long)t * TILE;
        #pragma unroll
        for (int q = 0; q < 4; q++) {
            long long n = base + lane + 32 * q;
            if (n < N) {
                ulonglong2* d = (ulonglong2*)(out + n * 480 + warp * 16);
                d[0] = make_ulonglong2(acc[q][0], acc[q][1]);
                d[1] = make_ulonglong2(acc[q][2], acc[q][3]);
                d[2] = make_ulonglong2(acc[q][4], acc[q][5]);
                d[3] = make_ulonglong2(acc[q][6], acc[q][7]);
            }
        }
        __syncthreads();
    }
}

// ---------------------------------------------------------------------------
// 1o: out[n,o,m] = sum_i x[n,i,m]*w[o,i,m];  I=O=64, M=3
// 8 warps: warp=grp owns outputs [8w,8w+8) (4 pairs); lane owns 3 nodes, TILE=96
// ---------------------------------------------------------------------------
__device__ void body_k1o(int cta, int ncta,
                         const float* __restrict__ x, const float* __restrict__ w,
                         float* __restrict__ out, int N, float* sm) {
    constexpr int I = 64, K = 192, TILE = 96, XROW = 194, WROW = 68;
    constexpr int WS = K * WROW;         // 13056
    constexpr int XB = TILE * XROW;      // 18624
    constexpr int CH = TILE * (K / 2);   // 9216

    float* ws  = sm;
    float* xb0 = sm + WS;
    float* xb1 = sm + WS + XB;

    int tid = threadIdx.x;
    for (int idx = tid; idx < 64 * 192; idx += NTHREADS)
        ws[(idx % 192) * WROW + (idx / 192)] = w[idx];     // ws[i*3+m][o]

    int warp = tid >> 5, lane = tid & 31;
    int ntiles = (N + TILE - 1) / TILE;
    int t0 = cta;

    if (t0 < ntiles) {
        long long base = (long long)t0 * TILE;
        for (int c = tid; c < CH; c += NTHREADS) {
            int nd = c / 96, cq = c % 96;
            long long n = base + nd;
            if (n < N) cp_async8(xb0 + nd * XROW + cq * 2, x + n * K + cq * 2);
        }
    }
    cp_commit();

    int par = 0;
    for (int t = t0; t < ntiles; t += ncta, par ^= 1) {
        int tn = t + ncta;
        if (tn < ntiles) {
            long long base = (long long)tn * TILE;
            float* dst = par ? xb0 : xb1;
            for (int c = tid; c < CH; c += NTHREADS) {
                int nd = c / 96, cq = c % 96;
                long long n = base + nd;
                if (n < N) cp_async8(dst + nd * XROW + cq * 2, x + n * K + cq * 2);
            }
        }
        cp_commit();
        cp_wait1();
        __syncthreads();

        float* xa = par ? xb1 : xb0;
        const float* xr[3];
        #pragma unroll
        for (int q = 0; q < 3; q++) xr[q] = xa + (lane + 32 * q) * XROW;

        ull acc[3][3][4];
        #pragma unroll
        for (int q = 0; q < 3; q++)
            #pragma unroll
            for (int m = 0; m < 3; m++)
                #pragma unroll
                for (int p = 0; p < 4; p++) acc[q][m][p] = 0ull;

        #pragma unroll 2
        for (int i = 0; i < I; i += 2) {
            float xs[3][6];
            #pragma unroll
            for (int q = 0; q < 3; q++) {
                *(float2*)&xs[q][0] = *(const float2*)(xr[q] + 3 * i);
                *(float2*)&xs[q][2] = *(const float2*)(xr[q] + 3 * i + 2);
                *(float2*)&xs[q][4] = *(const float2*)(xr[q] + 3 * i + 4);
            }
            #pragma unroll
            for (int s = 0; s < 2; s++)
                #pragma unroll
                for (int m = 0; m < 3; m++) {
                    const ulonglong2* wr =
                        (const ulonglong2*)(ws + ((i + s) * 3 + m) * WROW) + warp * 2;
                    ulonglong2 u0 = wr[0], u1 = wr[1];
                    #pragma unroll
                    for (int q = 0; q < 3; q++) {
                        ull v = dup2(xs[q][s * 3 + m]);
                        fma2(acc[q][m][0], v, u0.x); fma2(acc[q][m][1], v, u0.y);
                        fma2(acc[q][m][2], v, u1.x); fma2(acc[q][m][3], v, u1.y);
                    }
                }
        }

        long long base = (long long)t * TILE;
        #pragma unroll
        for (int q = 0; q < 3; q++) {
            long long n = base + lane + 32 * q;
            if (n < N) {
                float4 y4[6];
                float* y = (float*)y4;
                #pragma unroll
                for (int m = 0; m < 3; m++)
                    #pragma unroll
                    for (int p = 0; p < 4; p++) {
                        y[(2 * p) * 3 + m]     = ulo(acc[q][m][p]);
                        y[(2 * p + 1) * 3 + m] = uhi(acc[q][m][p]);
                    }
                float4* d = (float4*)(out + n * 480 + 128 + 24 * warp);
                #pragma unroll
                for (int e = 0; e < 6; e++) d[e] = y4[e];
            }
        }
        __syncthreads();
    }
}

// ---------------------------------------------------------------------------
// 2e: out[n,o,m] = sum_i x[n,i,m]*w[o,i,m];  I=O=32, M=5
// 8 warps: grp=warp>>1 owns outputs [8g,8g+8) (4 pairs); lane owns 2 nodes, TILE=128
// ---------------------------------------------------------------------------
__device__ void body_k2e(int cta, int ncta,
                         const float* __restrict__ x, const float* __restrict__ w,
                         float* __restrict__ out, int N, float* sm) {
    constexpr int I = 32, K = 160, TILE = 128, XROW = 162, WROW = 36;
    constexpr int WS = K * WROW;         // 5760
    constexpr int XB = TILE * XROW;      // 20736
    constexpr int CH = TILE * (K / 2);   // 10240

    float* ws  = sm;
    float* xb0 = sm + WS;
    float* xb1 = sm + WS + XB;

    int tid = threadIdx.x;
    for (int idx = tid; idx < 32 * 160; idx += NTHREADS)
        ws[(idx % 160) * WROW + (idx / 160)] = w[idx];     // ws[i*5+m][o]

    int warp = tid >> 5, lane = tid & 31;
    int grp  = warp >> 1;
    int nb   = (warp & 1) * 32 + lane;   // 0..63; nodes nb, nb+64
    int ntiles = (N + TILE - 1) / TILE;
    int t0 = cta;

    if (t0 < ntiles) {
        long long base = (long long)t0 * TILE;
        for (int c = tid; c < CH; c += NTHREADS) {
            int nd = c / 80, cq = c % 80;
            long long n = base + nd;
            if (n < N) cp_async8(xb0 + nd * XROW + cq * 2, x + n * K + cq * 2);
        }
    }
    cp_commit();

    int par = 0;
    for (int t = t0; t < ntiles; t += ncta, par ^= 1) {
        int tn = t + ncta;
        if (tn < ntiles) {
            long long base = (long long)tn * TILE;
            float* dst = par ? xb0 : xb1;
            for (int c = tid; c < CH; c += NTHREADS) {
                int nd = c / 80, cq = c % 80;
                long long n = base + nd;
                if (n < N) cp_async8(dst + nd * XROW + cq * 2, x + n * K + cq * 2);
            }
        }
        cp_commit();
        cp_wait1();
        __syncthreads();

        float* xa = par ? xb1 : xb0;
        const float* xr[2] = { xa + nb * XROW, xa + (nb + 64) * XROW };

        ull acc[2][5][4];
        #pragma unroll
        for (int q = 0; q < 2; q++)
            #pragma unroll
            for (int m = 0; m < 5; m++)
                #pragma unroll
                for (int p = 0; p < 4; p++) acc[q][m][p] = 0ull;

        #pragma unroll 2
        for (int i = 0; i < I; i += 2) {
            float xs[2][10];
            #pragma unroll
            for (int q = 0; q < 2; q++)
                #pragma unroll
                for (int u = 0; u < 5; u++)
                    *(float2*)&xs[q][2 * u] = *(const float2*)(xr[q] + 5 * i + 2 * u);
            #pragma unroll
            for (int s = 0; s < 2; s++)
                #pragma unroll
                for (int m = 0; m < 5; m++) {
                    const ulonglong2* wr =
                        (const ulonglong2*)(ws + ((i + s) * 5 + m) * WROW) + grp * 2;
                    ulonglong2 u0 = wr[0], u1 = wr[1];
                    #pragma unroll
                    for (int q = 0; q < 2; q++) {
                        ull v = dup2(xs[q][s * 5 + m]);
                        fma2(acc[q][m][0], v, u0.x); fma2(acc[q][m][1], v, u0.y);
                        fma2(acc[q][m][2], v, u1.x); fma2(acc[q][m][3], v, u1.y);
                    }
                }
        }

        long long base = (long long)t * TILE;
        #pragma unroll
        for (int q = 0; q < 2; q++) {
            long long n = base + nb + 64 * q;
            if (n < N) {
                float4 y4[10];
                float* y = (float*)y4;
                #pragma unroll
                for (int m = 0; m < 5; m++)
                    #pragma unroll
                    for (int p = 0; p < 4; p++) {
                        y[(2 * p) * 5 + m]     = ulo(acc[q][m][p]);
                        y[(2 * p + 1) * 5 + m] = uhi(acc[q][m][p]);
                    }
                float4* d = (float4*)(out + n * 480 + 320 + 40 * grp);
                #pragma unroll
                for (int e = 0; e < 10; e++) d[e] = y4[e];
            }
        }
        __syncthreads();
    }
}

// ---------------------------------------------------------------------------
// Fused persistent kernel: CTA ranges sized ~proportional to cycle demand
// ---------------------------------------------------------------------------
#define C0 65
#define C1 57
#define C2 30

__global__ __launch_bounds__(NTHREADS, 1)
void fused(const float* __restrict__ x0e, const float* __restrict__ x1o,
           const float* __restrict__ x2e, const float* __restrict__ w0e,
           const float* __restrict__ w1o, const float* __restrict__ w2e,
           const float* __restrict__ bias, float* __restrict__ out, int N) {
    extern __shared__ float sm[];
    int b = blockIdx.x;
    if (b < C0)            body_k0e(b, C0, x0e, w0e, bias, out, N, sm);
    else if (b < C0 + C1)  body_k1o(b - C0, C1, x1o, w1o, out, N, sm);
    else                   body_k2e(b - C0 - C1, C2, x2e, w2e, out, N, sm);
}

// ---------------------------------------------------------------------------
extern "C" void kernel_launch(void* const* d_in, const int* in_sizes, int n_in,
                              void* d_out, int out_size) {
    const float* x0e  = (const float*)d_in[0];
    const float* x1o  = (const float*)d_in[1];
    const float* x2e  = (const float*)d_in[2];
    const float* w0e  = (const float*)d_in[3];
    const float* w1o  = (const float*)d_in[4];
    const float* w2e  = (const float*)d_in[5];
    const float* bias = (const float*)d_in[6];
    float* out = (float*)d_out;
    int N = in_sizes[0] / 128;

    // k0e needs (16896 + 2*16896 + 128)*4 = 203264 B (largest of the three)
    int smem = (16896 + 2 * 16896 + 128) * 4;
    cudaFuncSetAttribute(fused, cudaFuncAttributeMaxDynamicSharedMemorySize, smem);

    fused<<<C0 + C1 + C2, NTHREADS, smem>>>(x0e, x1o, x2e, w0e, w1o, w2e, bias, out, N);
}

// round 14
// speedup vs baseline: 1.0021x; 1.0021x over previous
#include <cuda_runtime.h>
#include <cstdint>

using ull = unsigned long long;
#define NTHREADS 256

__device__ __forceinline__ void fma2(ull& d, ull a, ull b) {
    asm("fma.rn.f32x2 %0, %1, %2, %0;" : "+l"(d) : "l"(a), "l"(b));
}
__device__ __forceinline__ ull dup2(float x) {
    ull d; unsigned xi = __float_as_uint(x);
    asm("mov.b64 %0, {%1, %1};" : "=l"(d) : "r"(xi));
    return d;
}
__device__ __forceinline__ float ulo(ull v) { return __uint_as_float((unsigned)v); }
__device__ __forceinline__ float uhi(ull v) { return __uint_as_float((unsigned)(v >> 32)); }
__device__ __forceinline__ void cp_async8(void* dst, const void* src) {
    unsigned s = (unsigned)__cvta_generic_to_shared(dst);
    asm volatile("cp.async.ca.shared.global [%0], [%1], 8;" :: "r"(s), "l"(src));
}
__device__ __forceinline__ void cp_commit() { asm volatile("cp.async.commit_group;"); }
__device__ __forceinline__ void cp_wait1() { asm volatile("cp.async.wait_group 1;" ::: "memory"); }

// ---------------------------------------------------------------------------
// 0e: out[n,o] = sum_i x[n,i]*w[o,i] + bias[o];  I=O=128
// 8 warps: warp=grp owns outputs [16w,16w+16); lane owns 4 nodes (n=4,p=8)
// ---------------------------------------------------------------------------
__device__ void body_k0e(int cta, int ncta,
                         const float* __restrict__ x, const float* __restrict__ w,
                         const float* __restrict__ bias, float* __restrict__ out,
                         int N, float* sm) {
    constexpr int K = 128, TILE = 128, XROW = 132, WROW = 132;
    constexpr int WS = 128 * WROW;       // 16896
    constexpr int XB = TILE * XROW;      // 16896
    constexpr int CH = TILE * (K / 2);   // 8192

    float* ws  = sm;
    float* xb0 = sm + WS;
    float* xb1 = sm + WS + XB;
    float* bs  = sm + WS + 2 * XB;

    int tid = threadIdx.x;
    for (int idx = tid; idx < 128 * 128; idx += NTHREADS)
        ws[(idx & 127) * WROW + (idx >> 7)] = w[idx];      // ws[i][o]
    if (tid < 128) bs[tid] = bias[tid];

    int warp = tid >> 5, lane = tid & 31;
    int ntiles = (N + TILE - 1) / TILE;
    int t0 = cta;

    if (t0 < ntiles) {
        long long base = (long long)t0 * TILE;
        for (int c = tid; c < CH; c += NTHREADS) {
            int nd = c >> 6, cq = c & 63;
            long long n = base + nd;
            if (n < N) cp_async8(xb0 + nd * XROW + cq * 2, x + n * K + cq * 2);
        }
    }
    cp_commit();

    int par = 0;
    for (int t = t0; t < ntiles; t += ncta, par ^= 1) {
        int tn = t + ncta;
        if (tn < ntiles) {
            long long base = (long long)tn * TILE;
            float* dst = par ? xb0 : xb1;
            for (int c = tid; c < CH; c += NTHREADS) {
                int nd = c >> 6, cq = c & 63;
                long long n = base + nd;
                if (n < N) cp_async8(dst + nd * XROW + cq * 2, x + n * K + cq * 2);
            }
        }
        cp_commit();
        cp_wait1();
        __syncthreads();

        float* xa = par ? xb1 : xb0;
        const float4* xr[4];
        #pragma unroll
        for (int q = 0; q < 4; q++)
            xr[q] = (const float4*)(xa + (lane + 32 * q) * XROW);

        ull acc[4][8];
        const ull* bs2 = (const ull*)bs;
        #pragma unroll
        for (int q = 0; q < 4; q++)
            #pragma unroll
            for (int j = 0; j < 8; j++) acc[q][j] = bs2[warp * 8 + j];

        #pragma unroll 2
        for (int k4 = 0; k4 < K / 4; k4++) {
            float xs[4][4];
            #pragma unroll
            for (int q = 0; q < 4; q++) *(float4*)&xs[q][0] = xr[q][k4];
            #pragma unroll
            for (int kk = 0; kk < 4; kk++) {
                const ulonglong2* wr =
                    (const ulonglong2*)(ws + (k4 * 4 + kk) * WROW) + warp * 4;
                ulonglong2 u0 = wr[0], u1 = wr[1], u2 = wr[2], u3 = wr[3];
                #pragma unroll
                for (int q = 0; q < 4; q++) {
                    ull xd = dup2(xs[q][kk]);
                    fma2(acc[q][0], xd, u0.x); fma2(acc[q][1], xd, u0.y);
                    fma2(acc[q][2], xd, u1.x); fma2(acc[q][3], xd, u1.y);
                    fma2(acc[q][4], xd, u2.x); fma2(acc[q][5], xd, u2.y);
                    fma2(acc[q][6], xd, u3.x); fma2(acc[q][7], xd, u3.y);
                }
            }
        }

        long long base = (long long)t * TILE;
        #pragma unroll
        for (int q = 0; q < 4; q++) {
            long long n = base + lane + 32 * q;
            if (n < N) {
                ulonglong2* d = (ulonglong2*)(out + n * 480 + warp * 16);
                d[0] = make_ulonglong2(acc[q][0], acc[q][1]);
                d[1] = make_ulonglong2(acc[q][2], acc[q][3]);
                d[2] = make_ulonglong2(acc[q][4], acc[q][5]);
                d[3] = make_ulonglong2(acc[q][6], acc[q][7]);
            }
        }
        __syncthreads();
    }
}

// ---------------------------------------------------------------------------
// 1o: out[n,o,m] = sum_i x[n,i,m]*w[o,i,m];  I=O=64, M=3
// 8 warps: warp=grp owns outputs [8w,8w+8) (4 pairs); lane owns 3 nodes, TILE=96
// ---------------------------------------------------------------------------
__device__ void body_k1o(int cta, int ncta,
                         const float* __restrict__ x, const float* __restrict__ w,
                         float* __restrict__ out, int N, float* sm) {
    constexpr int I = 64, K = 192, TILE = 96, XROW = 194, WROW = 68;
    constexpr int WS = K * WROW;         // 13056
    constexpr int XB = TILE * XROW;      // 18624
    constexpr int CH = TILE * (K / 2);   // 9216

    float* ws  = sm;
    float* xb0 = sm + WS;
    float* xb1 = sm + WS + XB;

    int tid = threadIdx.x;
    for (int idx = tid; idx < 64 * 192; idx += NTHREADS)
        ws[(idx % 192) * WROW + (idx / 192)] = w[idx];     // ws[i*3+m][o]

    int warp = tid >> 5, lane = tid & 31;
    int ntiles = (N + TILE - 1) / TILE;
    int t0 = cta;

    if (t0 < ntiles) {
        long long base = (long long)t0 * TILE;
        for (int c = tid; c < CH; c += NTHREADS) {
            int nd = c / 96, cq = c % 96;
            long long n = base + nd;
            if (n < N) cp_async8(xb0 + nd * XROW + cq * 2, x + n * K + cq * 2);
        }
    }
    cp_commit();

    int par = 0;
    for (int t = t0; t < ntiles; t += ncta, par ^= 1) {
        int tn = t + ncta;
        if (tn < ntiles) {
            long long base = (long long)tn * TILE;
            float* dst = par ? xb0 : xb1;
            for (int c = tid; c < CH; c += NTHREADS) {
                int nd = c / 96, cq = c % 96;
                long long n = base + nd;
                if (n < N) cp_async8(dst + nd * XROW + cq * 2, x + n * K + cq * 2);
            }
        }
        cp_commit();
        cp_wait1();
        __syncthreads();

        float* xa = par ? xb1 : xb0;
        const float* xr[3];
        #pragma unroll
        for (int q = 0; q < 3; q++) xr[q] = xa + (lane + 32 * q) * XROW;

        ull acc[3][3][4];
        #pragma unroll
        for (int q = 0; q < 3; q++)
            #pragma unroll
            for (int m = 0; m < 3; m++)
                #pragma unroll
                for (int p = 0; p < 4; p++) acc[q][m][p] = 0ull;

        #pragma unroll 2
        for (int i = 0; i < I; i += 2) {
            float xs[3][6];
            #pragma unroll
            for (int q = 0; q < 3; q++) {
                *(float2*)&xs[q][0] = *(const float2*)(xr[q] + 3 * i);
                *(float2*)&xs[q][2] = *(const float2*)(xr[q] + 3 * i + 2);
                *(float2*)&xs[q][4] = *(const float2*)(xr[q] + 3 * i + 4);
            }
            #pragma unroll
            for (int s = 0; s < 2; s++)
                #pragma unroll
                for (int m = 0; m < 3; m++) {
                    const ulonglong2* wr =
                        (const ulonglong2*)(ws + ((i + s) * 3 + m) * WROW) + warp * 2;
                    ulonglong2 u0 = wr[0], u1 = wr[1];
                    #pragma unroll
                    for (int q = 0; q < 3; q++) {
                        ull v = dup2(xs[q][s * 3 + m]);
                        fma2(acc[q][m][0], v, u0.x); fma2(acc[q][m][1], v, u0.y);
                        fma2(acc[q][m][2], v, u1.x); fma2(acc[q][m][3], v, u1.y);
                    }
                }
        }

        long long base = (long long)t * TILE;
        #pragma unroll
        for (int q = 0; q < 3; q++) {
            long long n = base + lane + 32 * q;
            if (n < N) {
                float4 y4[6];
                float* y = (float*)y4;
                #pragma unroll
                for (int m = 0; m < 3; m++)
                    #pragma unroll
                    for (int p = 0; p < 4; p++) {
                        y[(2 * p) * 3 + m]     = ulo(acc[q][m][p]);
                        y[(2 * p + 1) * 3 + m] = uhi(acc[q][m][p]);
                    }
                float4* d = (float4*)(out + n * 480 + 128 + 24 * warp);
                #pragma unroll
                for (int e = 0; e < 6; e++) d[e] = y4[e];
            }
        }
        __syncthreads();
    }
}

// ---------------------------------------------------------------------------
// 2e: out[n,o,m] = sum_i x[n,i,m]*w[o,i,m];  I=O=32, M=5
// 8 warps: grp=warp>>1 owns outputs [8g,8g+8) (4 pairs); lane owns 2 nodes, TILE=128
// ---------------------------------------------------------------------------
__device__ void body_k2e(int cta, int ncta,
                         const float* __restrict__ x, const float* __restrict__ w,
                         float* __restrict__ out, int N, float* sm) {
    constexpr int I = 32, K = 160, TILE = 128, XROW = 162, WROW = 36;
    constexpr int WS = K * WROW;         // 5760
    constexpr int XB = TILE * XROW;      // 20736
    constexpr int CH = TILE * (K / 2);   // 10240

    float* ws  = sm;
    float* xb0 = sm + WS;
    float* xb1 = sm + WS + XB;

    int tid = threadIdx.x;
    for (int idx = tid; idx < 32 * 160; idx += NTHREADS)
        ws[(idx % 160) * WROW + (idx / 160)] = w[idx];     // ws[i*5+m][o]

    int warp = tid >> 5, lane = tid & 31;
    int grp  = warp >> 1;
    int nb   = (warp & 1) * 32 + lane;   // 0..63; nodes nb, nb+64
    int ntiles = (N + TILE - 1) / TILE;
    int t0 = cta;

    if (t0 < ntiles) {
        long long base = (long long)t0 * TILE;
        for (int c = tid; c < CH; c += NTHREADS) {
            int nd = c / 80, cq = c % 80;
            long long n = base + nd;
            if (n < N) cp_async8(xb0 + nd * XROW + cq * 2, x + n * K + cq * 2);
        }
    }
    cp_commit();

    int par = 0;
    for (int t = t0; t < ntiles; t += ncta, par ^= 1) {
        int tn = t + ncta;
        if (tn < ntiles) {
            long long base = (long long)tn * TILE;
            float* dst = par ? xb0 : xb1;
            for (int c = tid; c < CH; c += NTHREADS) {
                int nd = c / 80, cq = c % 80;
                long long n = base + nd;
                if (n < N) cp_async8(dst + nd * XROW + cq * 2, x + n * K + cq * 2);
            }
        }
        cp_commit();
        cp_wait1();
        __syncthreads();

        float* xa = par ? xb1 : xb0;
        const float* xr[2] = { xa + nb * XROW, xa + (nb + 64) * XROW };

        ull acc[2][5][4];
        #pragma unroll
        for (int q = 0; q < 2; q++)
            #pragma unroll
            for (int m = 0; m < 5; m++)
                #pragma unroll
                for (int p = 0; p < 4; p++) acc[q][m][p] = 0ull;

        #pragma unroll 2
        for (int i = 0; i < I; i += 2) {
            float xs[2][10];
            #pragma unroll
            for (int q = 0; q < 2; q++)
                #pragma unroll
                for (int u = 0; u < 5; u++)
                    *(float2*)&xs[q][2 * u] = *(const float2*)(xr[q] + 5 * i + 2 * u);
            #pragma unroll
            for (int s = 0; s < 2; s++)
                #pragma unroll
                for (int m = 0; m < 5; m++) {
                    const ulonglong2* wr =
                        (const ulonglong2*)(ws + ((i + s) * 5 + m) * WROW) + grp * 2;
                    ulonglong2 u0 = wr[0], u1 = wr[1];
                    #pragma unroll
                    for (int q = 0; q < 2; q++) {
                        ull v = dup2(xs[q][s * 5 + m]);
                        fma2(acc[q][m][0], v, u0.x); fma2(acc[q][m][1], v, u0.y);
                        fma2(acc[q][m][2], v, u1.x); fma2(acc[q][m][3], v, u1.y);
                    }
                }
        }

        long long base = (long long)t * TILE;
        #pragma unroll
        for (int q = 0; q < 2; q++) {
            long long n = base + nb + 64 * q;
            if (n < N) {
                float4 y4[10];
                float* y = (float*)y4;
                #pragma unroll
                for (int m = 0; m < 5; m++)
                    #pragma unroll
                    for (int p = 0; p < 4; p++) {
                        y[(2 * p) * 5 + m]     = ulo(acc[q][m][p]);
                        y[(2 * p + 1) * 5 + m] = uhi(acc[q][m][p]);
                    }
                float4* d = (float4*)(out + n * 480 + 320 + 40 * grp);
                #pragma unroll
                for (int e = 0; e < 10; e++) d[e] = y4[e];
            }
        }
        __syncthreads();
    }
}

// ---------------------------------------------------------------------------
// Fused persistent kernel: CTA ranges sized ~proportional to cycle demand
// ---------------------------------------------------------------------------
#define C0 65
#define C1 57
#define C2 30

__global__ __launch_bounds__(NTHREADS, 1)
void fused(const float* __restrict__ x0e, const float* __restrict__ x1o,
           const float* __restrict__ x2e, const float* __restrict__ w0e,
           const float* __restrict__ w1o, const float* __restrict__ w2e,
           const float* __restrict__ bias, float* __restrict__ out, int N) {
    extern __shared__ float sm[];
    int b = blockIdx.x;
    if (b < C0)            body_k0e(b, C0, x0e, w0e, bias, out, N, sm);
    else if (b < C0 + C1)  body_k1o(b - C0, C1, x1o, w1o, out, N, sm);
    else                   body_k2e(b - C0 - C1, C2, x2e, w2e, out, N, sm);
}

// ---------------------------------------------------------------------------
extern "C" void kernel_launch(void* const* d_in, const int* in_sizes, int n_in,
                              void* d_out, int out_size) {
    const float* x0e  = (const float*)d_in[0];
    const float* x1o  = (const float*)d_in[1];
    const float* x2e  = (const float*)d_in[2];
    const float* w0e  = (const float*)d_in[3];
    const float* w1o  = (const float*)d_in[4];
    const float* w2e  = (const float*)d_in[5];
    const float* bias = (const float*)d_in[6];
    float* out = (float*)d_out;
    int N = in_sizes[0] / 128;

    // k0e needs (16896 + 2*16896 + 128)*4 = 203264 B (largest of the three)
    int smem = (16896 + 2 * 16896 + 128) * 4;
    cudaFuncSetAttribute(fused, cudaFuncAttributeMaxDynamicSharedMemorySize, smem);

    fused<<<C0 + C1 + C2, NTHREADS, smem>>>(x0e, x1o, x2e, w0e, w1o, w2e, bias, out, N);
}